// round 4
// baseline (speedup 1.0000x reference)
#include <cuda_runtime.h>

// out = (Q K^T) V  ==  Q (K^T V)   — no softmax in the reference.
// B=1, H=16, S=4096, D=64, fp32.
//
// Phase A: partial M_hc = K_chunk^T V_chunk  (per head, per S-chunk) -> g_partial
// Phase B: M^T[h] = sum_c partial  (stored transposed: Mt[j][i])     -> g_Mt
// Phase C: out = Q @ M   (reads Q rows and Mt rows along d, float4)

#define NH      16
#define SS      4096
#define DD      64
#define CHUNKS  16
#define CHUNK_S (SS / CHUNKS)   // 256

__device__ float g_partial[NH * CHUNKS * DD * DD];  // 4 MB
__device__ float g_Mt[NH * DD * DD];                // 256 KB, Mt[h][j*64+i]

// ---------------------------------------------------------------------------
// Phase A: per-(head, chunk) partial K^T V.
// Block: 256 threads as 16x16; thread (ty,tx) owns M[ty*4..+3][tx*4..+3].
// ---------------------------------------------------------------------------
__global__ __launch_bounds__(256) void ktv_partial_kernel(
    const float* __restrict__ kg, const float* __restrict__ vg)
{
    __shared__ float ks[DD * DD];
    __shared__ float vs[DD * DD];

    const int bx    = blockIdx.x;
    const int h     = bx >> 4;
    const int chunk = bx & 15;
    const int tid   = threadIdx.x;
    const int ty    = tid >> 4;
    const int tx    = tid & 15;

    const float4* Kg = (const float4*)(kg + h * SS * DD + chunk * CHUNK_S * DD);
    const float4* Vg = (const float4*)(vg + h * SS * DD + chunk * CHUNK_S * DD);
    float4* ks4 = (float4*)ks;
    float4* vs4 = (float4*)vs;

    float acc[4][4] = {};

    for (int sub = 0; sub < CHUNK_S / 64; ++sub) {
        // Stage 64x64 K and V tiles (1024 float4 each), coalesced.
        #pragma unroll
        for (int i = 0; i < 4; ++i) {
            int idx = tid + i * 256;
            ks4[idx] = Kg[sub * 1024 + idx];
            vs4[idx] = Vg[sub * 1024 + idx];
        }
        __syncthreads();

        #pragma unroll 8
        for (int s = 0; s < 64; ++s) {
            float4 kk = *(const float4*)&ks[s * DD + ty * 4];  // broadcast (2 addrs/warp)
            float4 vv = *(const float4*)&vs[s * DD + tx * 4];  // conflict-free
            acc[0][0] += kk.x * vv.x; acc[0][1] += kk.x * vv.y;
            acc[0][2] += kk.x * vv.z; acc[0][3] += kk.x * vv.w;
            acc[1][0] += kk.y * vv.x; acc[1][1] += kk.y * vv.y;
            acc[1][2] += kk.y * vv.z; acc[1][3] += kk.y * vv.w;
            acc[2][0] += kk.z * vv.x; acc[2][1] += kk.z * vv.y;
            acc[2][2] += kk.z * vv.z; acc[2][3] += kk.z * vv.w;
            acc[3][0] += kk.w * vv.x; acc[3][1] += kk.w * vv.y;
            acc[3][2] += kk.w * vv.z; acc[3][3] += kk.w * vv.w;
        }
        __syncthreads();
    }

    float* P = g_partial + (h * CHUNKS + chunk) * DD * DD;
    #pragma unroll
    for (int r = 0; r < 4; ++r) {
        *(float4*)&P[(ty * 4 + r) * DD + tx * 4] =
            make_float4(acc[r][0], acc[r][1], acc[r][2], acc[r][3]);
    }
}

// ---------------------------------------------------------------------------
// Phase B: reduce 16 chunk-partials per head, write transposed Mt[h][j*64+i].
// Reads coalesced over e = i*64+j; scattered writes are only 256 KB total.
// ---------------------------------------------------------------------------
__global__ __launch_bounds__(256) void reduce_kernel()
{
    int base = blockIdx.x * 256 + threadIdx.x;   // grid 64 -> 16384 threads
    #pragma unroll
    for (int rep = 0; rep < 4; ++rep) {
        int o = base + rep * 16384;              // 0..65535
        int h = o >> 12;
        int e = o & 4095;                        // e = i*64 + j
        const float* P = g_partial + h * CHUNKS * 4096 + e;
        float sum = 0.f;
        #pragma unroll
        for (int c = 0; c < CHUNKS; ++c) sum += P[c * 4096];
        int i = e >> 6;
        int j = e & 63;
        g_Mt[h * 4096 + j * 64 + i] = sum;
    }
}

// ---------------------------------------------------------------------------
// Phase C: out = Q @ M. Block: 64 q-rows x 64 cols, 256 threads as 16x16,
// thread-tile 4x4, d-loop in float4 steps. Mt is XOR-swizzled in smem by
// (j>>2)&7 so column reads across lanes hit distinct 16B bank groups.
// ---------------------------------------------------------------------------
__global__ __launch_bounds__(256) void qm_kernel(
    const float* __restrict__ qg, float* __restrict__ outg)
{
    __shared__ float  qs[DD * DD];      // 16 KB, Q rows (natural layout)
    __shared__ float4 mt4[DD * 16];     // 4 KB,  Mt rows, swizzled float4s

    const int bx  = blockIdx.x;
    const int h   = bx >> 6;
    const int qt  = bx & 63;
    const int tid = threadIdx.x;
    const int ty  = tid >> 4;
    const int tx  = tid & 15;

    const float4* Qg = (const float4*)(qg + h * SS * DD + qt * 64 * DD);
    const float4* Mg = (const float4*)(g_Mt + h * 4096);
    float4* qs4 = (float4*)qs;

    #pragma unroll
    for (int it = 0; it < 4; ++it) {
        int o4 = tid + it * 256;                 // float4 index 0..1023
        qs4[o4] = Qg[o4];
        int j  = o4 >> 4;
        int d4 = o4 & 15;
        mt4[j * 16 + (d4 ^ ((j >> 2) & 7))] = Mg[o4];
    }
    __syncthreads();

    const int i0 = ty * 4;                       // q rows
    const int j0 = tx * 4;                       // out cols
    float acc[4][4] = {};

    #pragma unroll 4
    for (int d4 = 0; d4 < 16; ++d4) {
        float4 qv[4], mv[4];
        #pragma unroll
        for (int r = 0; r < 4; ++r)
            qv[r] = *(const float4*)&qs[(i0 + r) * DD + d4 * 4];
        #pragma unroll
        for (int c = 0; c < 4; ++c) {
            int j = j0 + c;
            mv[c] = mt4[j * 16 + (d4 ^ ((j >> 2) & 7))];
        }
        #pragma unroll
        for (int r = 0; r < 4; ++r) {
            #pragma unroll
            for (int c = 0; c < 4; ++c) {
                acc[r][c] += qv[r].x * mv[c].x + qv[r].y * mv[c].y
                           + qv[r].z * mv[c].z + qv[r].w * mv[c].w;
            }
        }
    }

    float* O = outg + h * SS * DD + qt * 64 * DD;
    #pragma unroll
    for (int r = 0; r < 4; ++r) {
        *(float4*)&O[(i0 + r) * DD + j0] =
            make_float4(acc[r][0], acc[r][1], acc[r][2], acc[r][3]);
    }
}

// ---------------------------------------------------------------------------
extern "C" void kernel_launch(void* const* d_in, const int* in_sizes, int n_in,
                              void* d_out, int out_size)
{
    const float* q = (const float*)d_in[0];
    const float* k = (const float*)d_in[1];
    const float* v = (const float*)d_in[2];
    float* out = (float*)d_out;
    (void)in_sizes; (void)n_in; (void)out_size;

    ktv_partial_kernel<<<NH * CHUNKS, 256>>>(k, v);
    reduce_kernel<<<64, 256>>>();
    qm_kernel<<<NH * 64, 256>>>(q, out);
}